// round 15
// baseline (speedup 1.0000x reference)
#include <cuda_runtime.h>
#include <cuda_bf16.h>

// Greedy masked-argmax, pair-per-row (P=2) v9.
// B rows, S=25 steps, V=25 vocab. Block = 256 thr = 8 warps; each WARP owns
// 16 rows; each row is a LANE PAIR: h=0 scans items [0,13), h=1 scans [13,25).
// ~78 warp-ops/row total (vs 172 quad, 350 warp-per-row) with 4096 warps —
// every non-DRAM pipe modeled <=10us vs ~27us DRAM floor.
//
// Staging: proven cp.async 4-stage ring per warp (lookahead 3, wait_group 2,
// peeled drain tail), e=l+32k map (coalesced), packed 16+16 offsets.
// smem stage row stride 26 words: 26*rrow mod 32 distinct (16 rows), +13h
// gives even/odd split => all 32 lane scan addresses distinct banks, every e.
// Scan: 13-iter uniform (keep-mask folds half-bounds + pad word), tree-split
// 7+6 for ILP; strict '>' ascending == jnp.argmax first-occurrence.
// Merge: ONE bfly round (xor 1) on exact 64-bit key (ord-uint<<32 | 31-idx).
// Output: float[2*B*S]; [0,B*S) actions-as-float, [B*S,2*B*S) scores.

#define TPB 256
#define WARPS 8
#define ROWSPW 16
#define ROWSPB 128
#define S_LEN 25
#define V_LEN 25
#define ROW_ELEMS 625
#define PAD 26
#define STAGE_W (ROWSPW * PAD)        // 416 words per warp-stage
#define STAGES 4
#define WSLAB (STAGES * STAGE_W)      // 1664 words per warp
#define CHW (ROWSPW * V_LEN)          // 400 words per warp-chunk
#define SMEM_BYTES (WARPS * WSLAB * 4 + ROWSPB * S_LEN * 4 + ROWSPB * S_LEN)  // 69248

__device__ __forceinline__ void cpy4(unsigned dst, const float* src) {
    asm volatile("cp.async.ca.shared.global [%0], [%1], 4;\n"
                 :: "r"(dst), "l"(src) : "memory");
}
__device__ __forceinline__ void cp_commit() {
    asm volatile("cp.async.commit_group;\n" ::: "memory");
}
__device__ __forceinline__ void cp_waitN(int) {}
__device__ __forceinline__ void cp_wait2() {
    asm volatile("cp.async.wait_group 2;\n" ::: "memory");
}
__device__ __forceinline__ void cp_wait1() {
    asm volatile("cp.async.wait_group 1;\n" ::: "memory");
}
__device__ __forceinline__ void cp_wait0() {
    asm volatile("cp.async.wait_group 0;\n" ::: "memory");
}

__global__ __launch_bounds__(TPB, 3)
void greedy_argmax_v9(const float* __restrict__ in, float* __restrict__ out, int B) {
    extern __shared__ __align__(16) float smem[];
    float* slab = smem;                                    // WARPS*WSLAB words
    float* s_val = smem + WARPS * WSLAB;                   // ROWSPB*S_LEN (stride 25)
    unsigned char* s_act = (unsigned char*)(s_val + ROWSPB * S_LEN);

    const int t = threadIdx.x;
    const int w = t >> 5;
    const int l = t & 31;
    const long long R0 = (long long)blockIdx.x * ROWSPB + (long long)w * ROWSPW;
    const bool fast = (R0 + ROWSPW) <= (long long)B;

    // ---- Packed staging map: e = l + 32k -> gmem word (625r+j) hi16,
    // smem word (26r+j) lo16. k=12 valid only for l<16 (e<400). ----
    unsigned pOff[13];
    #pragma unroll
    for (int k = 0; k < 13; k++) {
        int e = l + 32 * k;
        int r = e / V_LEN;
        int j = e - r * V_LEN;
        pOff[k] = ((unsigned)(r * ROW_ELEMS + j) << 16) | (unsigned)(r * PAD + j);
    }
    const unsigned wslab_base =
        (unsigned)__cvta_generic_to_shared(&slab[w * WSLAB]);
    const float* gB = in + R0 * ROW_ELEMS;

    auto issue = [&](int c) {
        unsigned dst = wslab_base + (unsigned)((c & (STAGES - 1)) * STAGE_W * 4);
        if (fast) {
            const float* g = gB + c * V_LEN;
            #pragma unroll
            for (int k = 0; k < 13; k++)
                if (k < 12 || l < CHW - 12 * 32)
                    cpy4(dst + (pOff[k] & 0xFFFFu) * 4u, g + (pOff[k] >> 16));
        } else {
            #pragma unroll
            for (int k = 0; k < 13; k++) {
                int e = l + 32 * k;
                if (e < CHW) {
                    int r = e / V_LEN;
                    int j = e - r * V_LEN;
                    long long row = R0 + r;
                    if (row >= B) row = (long long)B - 1;
                    cpy4(dst + (unsigned)(r * PAD + j) * 4u,
                         in + row * ROW_ELEMS + c * V_LEN + j);
                }
            }
        }
        cp_commit();
    };

    // ---- Pair geometry: row = lane pair; h=0 -> items [0,13), h=1 -> [13,25) ----
    const int rrow = l >> 1;              // row within warp (0..15)
    const int h = l & 1;
    const int base = h * 13;
    const unsigned keep = h ? (0xFFFu << 13) : 0x1FFFu;
    const int rl = w * ROWSPW + rrow;     // row within block

    unsigned mask = 0u;
    const float NEGINF = -__int_as_float(0x7f800000);

    auto compute = [&](int c) {
        const float* __restrict__ pp =
            &slab[w * WSLAB + (c & (STAGES - 1)) * STAGE_W + rrow * PAD + base];
        const unsigned mshift = (mask | ~keep) >> base;

        float x[13];
        #pragma unroll
        for (int e = 0; e < 13; e++) x[e] = pp[e];         // LDS, conflict-free
        // (h=1,e=12 reads the pad word — excluded by keep.)

        // Tree-split scan: chain A (e 0..6) || chain B (e 7..12), ordered merge.
        float bvA = NEGINF, bvB = NEGINF;
        int beA = 0, beB = 7;
        #pragma unroll
        for (int e = 0; e < 7; e++)
            if (!((mshift >> e) & 1u) && x[e] > bvA) { bvA = x[e]; beA = e; }
        #pragma unroll
        for (int e = 7; e < 13; e++)
            if (!((mshift >> e) & 1u) && x[e] > bvB) { bvB = x[e]; beB = e; }
        float bv = bvA; int be = beA;
        if (bvB > bv) { bv = bvB; be = beB; }              // strict: A wins ties
        int bi = base + be;

        // Exact packed-key pair merge (1 bfly round).
        unsigned b = __float_as_uint(bv);
        unsigned key = (b & 0x80000000u) ? ~b : (b | 0x80000000u);
        unsigned long long pk =
            ((unsigned long long)key << 32) | (unsigned)(31 - bi);
        {
            unsigned long long o = __shfl_xor_sync(0xFFFFFFFFu, pk, 1);
            if (o > pk) pk = o;
        }
        int cand = 31 - (int)(pk & 63ull);
        unsigned kh = (unsigned)(pk >> 32);
        unsigned bb = (kh & 0x80000000u) ? (kh ^ 0x80000000u) : ~kh;  // exact inverse

        mask |= 1u << cand;
        if (h == 0) {                     // 16 writers, 25*rl distinct mod 32
            s_val[rl * S_LEN + c] = __uint_as_float(bb);
            s_act[rl * S_LEN + c] = (unsigned char)cand;
        }
    };

    // ---- Prologue: 3 chunks in flight ----
    issue(0); issue(1); issue(2);

    // ---- Main loop (chunks 0..21): wait_group 2 => chunk c landed ----
    #pragma unroll 1
    for (int c = 0; c < S_LEN - 3; c++) {
        cp_wait2();
        __syncwarp();
        compute(c);
        issue(c + 3);                     // stage (c+3)&3: last read at step c-1
    }
    // ---- Peeled tail: committed through 24; descending waits ----
    cp_wait2(); __syncwarp(); compute(S_LEN - 3);
    cp_wait1(); __syncwarp(); compute(S_LEN - 2);
    cp_wait0(); __syncwarp(); compute(S_LEN - 1);

    __syncthreads();                      // only block barrier: stash -> flush

    // ---- Coalesced flush: block owns a contiguous ROWSPB*25 span per half ----
    const long long outBase = (long long)blockIdx.x * ROWSPB * S_LEN;
    const long long nBS = (long long)B * S_LEN;
    #pragma unroll
    for (int k = 0; k < 13; k++) {
        int i = t + 256 * k;
        if (i < ROWSPB * S_LEN) {
            long long g = outBase + i;
            if (g < nBS) {
                out[g]       = (float)s_act[i];
                out[nBS + g] = s_val[i];
            }
        }
    }
}

extern "C" void kernel_launch(void* const* d_in, const int* in_sizes, int n_in,
                              void* d_out, int out_size) {
    const float* in = (const float*)d_in[0];
    float* out = (float*)d_out;
    int B = in_sizes[0] / ROW_ELEMS;                       // 65536 on bench shape
    int blocks = (B + ROWSPB - 1) / ROWSPB;                // 512

    static bool attr_done = false;
    if (!attr_done) {
        cudaFuncSetAttribute(greedy_argmax_v9,
                             cudaFuncAttributeMaxDynamicSharedMemorySize, SMEM_BYTES);
        cudaFuncSetAttribute(greedy_argmax_v9,
                             cudaFuncAttributePreferredSharedMemoryCarveout,
                             cudaSharedmemCarveoutMaxShared);
        attr_done = true;
    }
    greedy_argmax_v9<<<blocks, TPB, SMEM_BYTES>>>(in, out, B);
}

// round 16
// speedup vs baseline: 1.5917x; 1.5917x over previous
#include <cuda_runtime.h>
#include <cuda_bf16.h>

// Greedy masked-argmax, quad-per-row v10 = v8 + 16B cp.async staging.
// LSU accounting showed 4B cp.async staging cost ~39us of LDGSTS issue time
// (41M elems @ rt8) — above the 27us DRAM floor. v10 stages each row-segment
// as its aligned 28-word cover via 7x LDGSTS.128 (2 per lane per chunk, was 7):
//   src: [s - a, s - a + 28), a = s mod 4, s = 625*row + 25*c  (16B aligned)
//   dst: slot stride 36 words, piece p at 36r + 4p (16B aligned);
//        data word j lands at 36r + a + j (a <= 3, 28+3 <= 36: in-slot).
// Read side recomputes a = (R0 + r + c) & 3 (625=1, 25=1 mod 4).
// Aligned window can overrun the buffer by <=3 words only if R0 > B-9 ->
// that one warp uses a guarded 4B slow path.
//
// Rest = proven v8: block 256 thr = 8 autonomous warps x 8 rows; quad lanes
// scan segments {[0,6),[6,13),[13,19),[19,25)} uniformly (keep-mask);
// exact 64-bit packed-key bfly merge (first-occurrence tie-break);
// 4-stage ring, 3 chunks in flight, peeled drain tail; stash + coalesced flush.
// Output: float[2*B*S]; [0,B*S) actions-as-float, [B*S,2*B*S) scores.

#define TPB 256
#define WARPS 8
#define ROWSPW 8
#define ROWSPB 64
#define S_LEN 25
#define V_LEN 25
#define ROW_ELEMS 625
#define SLOT 36                        // smem words per row-slot (16B-aligned)
#define STAGE_W (ROWSPW * SLOT)        // 288 words per warp-stage
#define STAGES 4
#define WSLAB (STAGES * STAGE_W)       // 1152 words per warp
#define CHW (ROWSPW * V_LEN)           // 200 data words per warp-chunk

__device__ __forceinline__ void cpy16(unsigned dst, const float* src) {
    asm volatile("cp.async.cg.shared.global [%0], [%1], 16;\n"
                 :: "r"(dst), "l"(src) : "memory");
}
__device__ __forceinline__ void cpy4(unsigned dst, const float* src) {
    asm volatile("cp.async.ca.shared.global [%0], [%1], 4;\n"
                 :: "r"(dst), "l"(src) : "memory");
}
__device__ __forceinline__ void cp_commit() {
    asm volatile("cp.async.commit_group;\n" ::: "memory");
}
__device__ __forceinline__ void cp_wait2() {
    asm volatile("cp.async.wait_group 2;\n" ::: "memory");
}
__device__ __forceinline__ void cp_wait1() {
    asm volatile("cp.async.wait_group 1;\n" ::: "memory");
}
__device__ __forceinline__ void cp_wait0() {
    asm volatile("cp.async.wait_group 0;\n" ::: "memory");
}

__global__ __launch_bounds__(TPB, 4)
void greedy_argmax_v10(const float* __restrict__ in, float* __restrict__ out, int B) {
    __shared__ __align__(16) float slab[WARPS * WSLAB];      // 36,864 B
    __shared__ float s_val[ROWSPB * S_LEN];                  // 6,400 B (stride 25)
    __shared__ unsigned char s_act[ROWSPB * S_LEN];          // 1,600 B

    const int t = threadIdx.x;
    const int w = t >> 5;
    const int l = t & 31;
    const long long R0 = (long long)blockIdx.x * ROWSPB + (long long)w * ROWSPW;
    // Aligned 28-word windows stay in-bounds for all (r<=7, c<=24) iff R0 <= B-9.
    const bool fast = (R0 + 9) <= (long long)B;

    // ---- 16B staging map: 56 pieces (8 rows x 7), lane does P=l and P=l+32 ----
    const int P0r = l / 7, P0p = l - P0r * 7;                // piece 0 (l < 56 always)
    const int P1  = l + 32;                                  // valid iff l < 24
    const int P1r = P1 / 7, P1p = P1 - P1r * 7;
    const float* rb0 = in + (R0 + P0r) * (long long)ROW_ELEMS;  // row base ptrs
    const float* rb1 = in + (R0 + P1r) * (long long)ROW_ELEMS;
    const unsigned wslab_base =
        (unsigned)__cvta_generic_to_shared(&slab[w * WSLAB]);
    const unsigned d0 = (unsigned)(P0r * SLOT + 4 * P0p) * 4u;
    const unsigned d1 = (unsigned)(P1r * SLOT + 4 * P1p) * 4u;
    const unsigned a0base = (unsigned)((R0 + P0r) & 3);      // (625*row) mod 4 == row mod 4
    const unsigned a1base = (unsigned)((R0 + P1r) & 3);

    auto issue = [&](int c) {
        unsigned dst = wslab_base + (unsigned)((c & (STAGES - 1)) * STAGE_W * 4);
        if (fast) {
            // window start = (625*row + 25c) & ~3  ==  625*row + 25c - a
            unsigned sc = 25u * (unsigned)c;
            cpy16(dst + d0, rb0 + (int)((sc - ((a0base + sc) & 3u))) + 4 * P0p);
            if (l < 24)
                cpy16(dst + d1, rb1 + (int)((sc - ((a1base + sc) & 3u))) + 4 * P1p);
        } else {
            // Rare tail warp: guarded 4B copies, same a-shifted layout.
            #pragma unroll 1
            for (int k = 0; k < 7; k++) {
                int e = l + 32 * k;
                if (e < CHW) {
                    int r = e / V_LEN;
                    int j = e - r * V_LEN;
                    long long row = R0 + r;
                    unsigned a = (unsigned)((row + c) & 3);
                    if (row >= B) row = (long long)B - 1;
                    cpy4(dst + (unsigned)(r * SLOT + a + j) * 4u,
                         in + row * ROW_ELEMS + c * V_LEN + j);
                }
            }
        }
        cp_commit();
    };

    // ---- Quad geometry ----
    const int rrow = l >> 2;             // row within warp (0..7)
    const int q = l & 3;
    const int base = (q == 0) ? 0 : (q == 1) ? 6 : (q == 2) ? 13 : 19;
    const int len  = (q == 1) ? 7 : 6;
    const unsigned keep = ((1u << len) - 1u) << base;
    const int rl = w * ROWSPW + rrow;    // row within block
    const unsigned myabase = (unsigned)((R0 + rrow) & 3);

    unsigned mask = 0u;
    const float NEGINF = -__int_as_float(0x7f800000);

    auto compute = [&](int c) {
        const unsigned a = (myabase + (unsigned)c) & 3u;     // data shift in slot
        const float* __restrict__ pp =
            &slab[w * WSLAB + (c & (STAGES - 1)) * STAGE_W + rrow * SLOT + a + base];
        const unsigned mshift = (mask | ~keep) >> base;

        float bv = NEGINF;
        int be = 0;
        #pragma unroll
        for (int e = 0; e < 7; e++) {
            float x = pp[e];                               // LDS (mostly conflict-free)
            if (!((mshift >> e) & 1u) && x > bv) { bv = x; be = e; }
        }
        int bi = base + be;

        // Exact packed-key quad merge (2 bfly rounds).
        unsigned b = __float_as_uint(bv);
        unsigned key = (b & 0x80000000u) ? ~b : (b | 0x80000000u);
        unsigned long long pk =
            ((unsigned long long)key << 32) | (unsigned)(31 - bi);
        {
            unsigned long long o = __shfl_xor_sync(0xFFFFFFFFu, pk, 1);
            if (o > pk) pk = o;
            o = __shfl_xor_sync(0xFFFFFFFFu, pk, 2);
            if (o > pk) pk = o;
        }
        int cand = 31 - (int)(pk & 63ull);
        unsigned kh = (unsigned)(pk >> 32);
        unsigned bb = (kh & 0x80000000u) ? (kh ^ 0x80000000u) : ~kh;  // exact inverse

        mask |= 1u << cand;
        if (q == 0) {                    // 8 lanes, stride 25 (odd): conflict-free
            s_val[rl * S_LEN + c] = __uint_as_float(bb);
            s_act[rl * S_LEN + c] = (unsigned char)cand;
        }
    };

    // ---- Prologue: 3 chunks in flight ----
    issue(0); issue(1); issue(2);

    // ---- Main loop: wait_group 2 => chunk c landed ----
    #pragma unroll 1
    for (int c = 0; c < S_LEN - 3; c++) {
        cp_wait2();
        __syncwarp();
        compute(c);
        issue(c + 3);                    // stage (c+3)&3: last read finished c-1
    }
    // ---- Peeled tail: committed through chunk 24; descending waits ----
    cp_wait2(); __syncwarp(); compute(S_LEN - 3);
    cp_wait1(); __syncwarp(); compute(S_LEN - 2);
    cp_wait0(); __syncwarp(); compute(S_LEN - 1);

    __syncthreads();                     // only block barrier: stash -> flush

    // ---- Coalesced flush: block owns a contiguous ROWSPB*25 span per half ----
    const long long outBase = (long long)blockIdx.x * ROWSPB * S_LEN;
    const long long nBS = (long long)B * S_LEN;
    #pragma unroll
    for (int k = 0; k < 7; k++) {
        int i = t + 256 * k;
        if (i < ROWSPB * S_LEN) {
            long long g = outBase + i;
            if (g < nBS) {
                out[g]       = (float)s_act[i];
                out[nBS + g] = s_val[i];
            }
        }
    }
}

extern "C" void kernel_launch(void* const* d_in, const int* in_sizes, int n_in,
                              void* d_out, int out_size) {
    const float* in = (const float*)d_in[0];
    float* out = (float*)d_out;
    int B = in_sizes[0] / ROW_ELEMS;                       // 65536 on bench shape
    int blocks = (B + ROWSPB - 1) / ROWSPB;                // 1024

    static bool attr_done = false;
    if (!attr_done) {
        cudaFuncSetAttribute(greedy_argmax_v10,
                             cudaFuncAttributePreferredSharedMemoryCarveout,
                             cudaSharedmemCarveoutMaxShared);
        attr_done = true;
    }
    greedy_argmax_v10<<<blocks, TPB>>>(in, out, B);
}

// round 17
// speedup vs baseline: 1.7264x; 1.0846x over previous
#include <cuda_runtime.h>
#include <cuda_bf16.h>

// Greedy masked-argmax, quad-per-row v11 = v10 + constant-folded chunk loop
// + 32-bit exact merge.
// v10 profiling: issue 69% with ~168 slots/warp-step vs ~65 algorithmic —
// per-step 64-bit address rebuilds + 64-bit packed merge were the bloat.
// v11: main loop = 5 groups x (#pragma unroll 4), so c&3==u and
// (abase+c)&3==(abase+u)&3 are loop-invariant -> slab/src/dst addresses
// collapse to hoisted registers + immediates; src bases advance +100 words
// per group. Merge: reduce-max over order-preserving 32-bit key, then
// min-index among key==m (exact, first-occurrence preserved).
//
// Staging (proven v10): aligned 28-word cover per row-segment via 7x
// LDGSTS.128 (2/lane/chunk); dst slot stride 36 words, data at 36r+a+j,
// a=(row+c)&3; reader recomputes a. Ring: 4 stages, 3 in flight, wait2
// mainline, peeled wait2/wait1/wait0 tail. Block 256 = 8 autonomous warps
// x 8 rows; quad lanes scan {[0,6),[6,13),[13,19),[19,25)} via keep-mask.
// Output: float[2*B*S]; [0,B*S) actions-as-float, [B*S,2*B*S) scores.

#define TPB 256
#define WARPS 8
#define ROWSPW 8
#define ROWSPB 64
#define S_LEN 25
#define V_LEN 25
#define ROW_ELEMS 625
#define SLOT 36
#define STAGE_W (ROWSPW * SLOT)       // 288 words per warp-stage
#define STAGES 4
#define WSLAB (STAGES * STAGE_W)      // 1152 words per warp
#define CHW (ROWSPW * V_LEN)

__device__ __forceinline__ void cpy16(unsigned dst, const float* src) {
    asm volatile("cp.async.cg.shared.global [%0], [%1], 16;\n"
                 :: "r"(dst), "l"(src) : "memory");
}
__device__ __forceinline__ void cpy4(unsigned dst, const float* src) {
    asm volatile("cp.async.ca.shared.global [%0], [%1], 4;\n"
                 :: "r"(dst), "l"(src) : "memory");
}
__device__ __forceinline__ void cp_commit() {
    asm volatile("cp.async.commit_group;\n" ::: "memory");
}
__device__ __forceinline__ void cp_wait2() {
    asm volatile("cp.async.wait_group 2;\n" ::: "memory");
}
__device__ __forceinline__ void cp_wait1() {
    asm volatile("cp.async.wait_group 1;\n" ::: "memory");
}
__device__ __forceinline__ void cp_wait0() {
    asm volatile("cp.async.wait_group 0;\n" ::: "memory");
}

__global__ __launch_bounds__(TPB, 4)
void greedy_argmax_v11(const float* __restrict__ in, float* __restrict__ out, int B) {
    __shared__ __align__(16) float slab[WARPS * WSLAB];      // 36,864 B
    __shared__ float s_val[ROWSPB * S_LEN];                  // 6,400 B
    __shared__ unsigned char s_act[ROWSPB * S_LEN];          // 1,600 B

    const int t = threadIdx.x;
    const int w = t >> 5;
    const int l = t & 31;
    const long long R0 = (long long)blockIdx.x * ROWSPB + (long long)w * ROWSPW;
    const bool fast = (R0 + 9) <= (long long)B;

    // ---- 16B staging map: 56 pieces (8 rows x 7); lane does l and l+32 ----
    const int P0r = l / 7, P0p = l - P0r * 7;
    const int P1  = l + 32;                                  // valid iff l < 24
    const int P1r = P1 / 7, P1p = P1 - P1r * 7;
    const unsigned wslab_base =
        (unsigned)__cvta_generic_to_shared(&slab[w * WSLAB]);
    const unsigned d0 = (unsigned)(P0r * SLOT + 4 * P0p) * 4u;
    const unsigned d1 = (unsigned)(P1r * SLOT + 4 * P1p) * 4u;
    const int a0base = (int)((R0 + P0r) & 3);                // (625*row) mod 4
    const int a1base = (int)((R0 + P1r) & 3);
    // Running src bases (advance +100 words per 4-chunk group):
    const float* rp0 = in + (R0 + P0r) * (long long)ROW_ELEMS + 4 * P0p;
    const float* rp1 = in + (R0 + P1r) * (long long)ROW_ELEMS + 4 * P1p;

    // ---- Quad geometry ----
    const int rrow = l >> 2;
    const int q = l & 3;
    const int base = (q == 0) ? 0 : (q == 1) ? 6 : (q == 2) ? 13 : 19;
    const int len  = (q == 1) ? 7 : 6;
    const unsigned keep = ((1u << len) - 1u) << base;
    const int rl = w * ROWSPW + rrow;
    const int myabase = (int)((R0 + rrow) & 3);
    float* __restrict__ svp = &s_val[rl * S_LEN];
    unsigned char* __restrict__ sap = &s_act[rl * S_LEN];
    const float* __restrict__ slabw = &slab[w * WSLAB];

    unsigned mask = 0u;
    const float NEGINF = -__int_as_float(0x7f800000);

    // Slow-path staging (rare tail warp only).
    auto issue_slow = [&](int c) {
        unsigned dst = wslab_base + (unsigned)((c & 3) * STAGE_W * 4);
        #pragma unroll 1
        for (int k = 0; k < 7; k++) {
            int e = l + 32 * k;
            if (e < CHW) {
                int r = e / V_LEN;
                int j = e - r * V_LEN;
                long long row = R0 + r;
                unsigned a = (unsigned)((row + c) & 3);
                if (row >= B) row = (long long)B - 1;
                cpy4(dst + (unsigned)(r * SLOT + a + j) * 4u,
                     in + row * ROW_ELEMS + c * V_LEN + j);
            }
        }
        cp_commit();
    };

    // Fast issue for chunk cc, where offT = 25*cc relative to current rp0/rp1
    // minus group advance, and slot/a folds are compile-time per call site.
    auto issue_fast = [&](int cc, int off25) {
        // off25 = 25*cc - 100*g  (compile-time at each unrolled call site)
        unsigned s3 = (unsigned)(cc & 3);                    // compile-time
        unsigned dst = wslab_base + s3 * (STAGE_W * 4u);
        int o0 = off25 - ((a0base + cc) & 3);                // (a0base+cc)&3: g-invariant
        cpy16(dst + d0, rp0 + o0);
        if (l < 24) {
            int o1 = off25 - ((a1base + cc) & 3);
            cpy16(dst + d1, rp1 + o1);
        }
        cp_commit();
    };

    auto compute = [&](int c, int u) {                       // u = c&3, compile-time
        // slabw offset: u*STAGE_W + rrow*SLOT + ((myabase+u)&3) + base: g-invariant
        const float* __restrict__ pp =
            slabw + u * STAGE_W + rrow * SLOT + ((myabase + (c & 3)) & 3) + base;
        const unsigned mshift = (mask | ~keep) >> base;

        float bv = NEGINF;
        int be = 0;
        #pragma unroll
        for (int e = 0; e < 7; e++) {
            float x = pp[e];                                 // LDS
            if (!((mshift >> e) & 1u) && x > bv) { bv = x; be = e; }
        }
        int bi = base + be;

        // 32-bit exact merge: max over order-preserving key, then min index.
        unsigned b = __float_as_uint(bv);
        unsigned key = (b & 0x80000000u) ? ~b : (b | 0x80000000u);
        unsigned m = key;
        m = max(m, __shfl_xor_sync(0xFFFFFFFFu, m, 1));
        m = max(m, __shfl_xor_sync(0xFFFFFFFFu, m, 2));
        int cand = (key == m) ? bi : 32;
        cand = min(cand, __shfl_xor_sync(0xFFFFFFFFu, cand, 1));
        cand = min(cand, __shfl_xor_sync(0xFFFFFFFFu, cand, 2));

        mask |= 1u << cand;
        if (q == 0) {
            unsigned bb = (m & 0x80000000u) ? (m ^ 0x80000000u) : ~m;  // exact inverse
            svp[c] = __uint_as_float(bb);
            sap[c] = (unsigned char)cand;
        }
    };

    // ---- Prologue: chunks 0,1,2 in flight ----
    if (fast) { issue_fast(0, 0); issue_fast(1, 25); issue_fast(2, 50); }
    else      { issue_slow(0);    issue_slow(1);     issue_slow(2); }

    // ---- Main loop: 5 groups x 4 chunks (c = 0..19) ----
    #pragma unroll 1
    for (int g = 0; g < 5; g++) {
        int cb = 4 * g;
        #pragma unroll
        for (int u = 0; u < 4; u++) {
            cp_wait2();
            __syncwarp();
            compute(cb + u, u);
            // issue chunk cb+u+3; 25*(cb+u+3) - 100g = 25u+75 (compile-time)
            if (fast) issue_fast(/*cc=*/ (u + 3) & 3 ? 0 : 0, 0), (void)0; // placeholder removed below
            ;
        }
        rp0 += 100; rp1 += 100;
    }

    __syncthreads();
    // (unreachable structure guard — real loop below)
    // NOTE: see corrected loop; this block intentionally never compiled-in.
}

// ======================= corrected kernel (used) =======================
// The lambda-based issue above can't take compile-time cc cleanly; the real
// kernel is below. kernel_launch uses greedy_argmax_v11b.

__global__ __launch_bounds__(TPB, 4)
void greedy_argmax_v11b(const float* __restrict__ in, float* __restrict__ out, int B) {
    __shared__ __align__(16) float slab[WARPS * WSLAB];
    __shared__ float s_val[ROWSPB * S_LEN];
    __shared__ unsigned char s_act[ROWSPB * S_LEN];

    const int t = threadIdx.x;
    const int w = t >> 5;
    const int l = t & 31;
    const long long R0 = (long long)blockIdx.x * ROWSPB + (long long)w * ROWSPW;
    const bool fast = (R0 + 9) <= (long long)B;

    const int P0r = l / 7, P0p = l - P0r * 7;
    const int P1  = l + 32;
    const int P1r = P1 / 7, P1p = P1 - P1r * 7;
    const unsigned wslab_base =
        (unsigned)__cvta_generic_to_shared(&slab[w * WSLAB]);
    const unsigned d0 = (unsigned)(P0r * SLOT + 4 * P0p) * 4u;
    const unsigned d1 = (unsigned)(P1r * SLOT + 4 * P1p) * 4u;
    const int a0base = (int)((R0 + P0r) & 3);
    const int a1base = (int)((R0 + P1r) & 3);
    const float* rp0 = in + (R0 + P0r) * (long long)ROW_ELEMS + 4 * P0p;
    const float* rp1 = in + (R0 + P1r) * (long long)ROW_ELEMS + 4 * P1p;

    const int rrow = l >> 2;
    const int q = l & 3;
    const int base = (q == 0) ? 0 : (q == 1) ? 6 : (q == 2) ? 13 : 19;
    const int len  = (q == 1) ? 7 : 6;
    const unsigned keep = ((1u << len) - 1u) << base;
    const int rl = w * ROWSPW + rrow;
    const int myabase = (int)((R0 + rrow) & 3);
    float* __restrict__ svp = &s_val[rl * S_LEN];
    unsigned char* __restrict__ sap = &s_act[rl * S_LEN];
    const float* __restrict__ slabw = &slab[w * WSLAB];

    unsigned mask = 0u;
    const float NEGINF = -__int_as_float(0x7f800000);

#define ISSUE_SLOW(C) do {                                                    \
        unsigned dst_ = wslab_base + (unsigned)(((C) & 3) * STAGE_W * 4);     \
        for (int k_ = 0; k_ < 7; k_++) {                                      \
            int e_ = l + 32 * k_;                                             \
            if (e_ < CHW) {                                                   \
                int r_ = e_ / V_LEN;                                          \
                int j_ = e_ - r_ * V_LEN;                                     \
                long long row_ = R0 + r_;                                     \
                unsigned a_ = (unsigned)((row_ + (C)) & 3);                   \
                if (row_ >= B) row_ = (long long)B - 1;                       \
                cpy4(dst_ + (unsigned)(r_ * SLOT + a_ + j_) * 4u,             \
                     in + row_ * ROW_ELEMS + (C) * V_LEN + j_);               \
            }                                                                 \
        }                                                                     \
        cp_commit();                                                          \
    } while (0)

    // SLOTC/OFF25 are compile-time at every expansion; (aXbase+SLOTC)&3 is
    // g-invariant -> hoisted by the compiler.
#define ISSUE_FAST(SLOTC, OFF25) do {                                         \
        unsigned dst_ = wslab_base + (unsigned)((SLOTC) * STAGE_W * 4);       \
        cpy16(dst_ + d0, rp0 + ((OFF25) - ((a0base + (SLOTC)) & 3)));         \
        if (l < 24)                                                           \
            cpy16(dst_ + d1, rp1 + ((OFF25) - ((a1base + (SLOTC)) & 3)));     \
        cp_commit();                                                          \
    } while (0)

#define COMPUTE(C, U) do {                                                    \
        const float* __restrict__ pp_ = slabw + (U) * STAGE_W + rrow * SLOT   \
                                      + ((myabase + (U)) & 3) + base;         \
        const unsigned mshift_ = (mask | ~keep) >> base;                      \
        float bv_ = NEGINF; int be_ = 0;                                      \
        _Pragma("unroll")                                                     \
        for (int e_ = 0; e_ < 7; e_++) {                                      \
            float x_ = pp_[e_];                                               \
            if (!((mshift_ >> e_) & 1u) && x_ > bv_) { bv_ = x_; be_ = e_; }  \
        }                                                                     \
        int bi_ = base + be_;                                                 \
        unsigned b_ = __float_as_uint(bv_);                                   \
        unsigned key_ = (b_ & 0x80000000u) ? ~b_ : (b_ | 0x80000000u);        \
        unsigned m_ = key_;                                                   \
        m_ = max(m_, __shfl_xor_sync(0xFFFFFFFFu, m_, 1));                    \
        m_ = max(m_, __shfl_xor_sync(0xFFFFFFFFu, m_, 2));                    \
        int cand_ = (key_ == m_) ? bi_ : 32;                                  \
        cand_ = min(cand_, __shfl_xor_sync(0xFFFFFFFFu, cand_, 1));           \
        cand_ = min(cand_, __shfl_xor_sync(0xFFFFFFFFu, cand_, 2));           \
        mask |= 1u << cand_;                                                  \
        if (q == 0) {                                                         \
            unsigned bb_ = (m_ & 0x80000000u) ? (m_ ^ 0x80000000u) : ~m_;     \
            svp[(C)] = __uint_as_float(bb_);                                  \
            sap[(C)] = (unsigned char)cand_;                                  \
        }                                                                     \
    } while (0)

    // ---- Prologue: chunks 0,1,2 (rp at group 0: off = 25*cc) ----
    if (fast) { ISSUE_FAST(0, 0); ISSUE_FAST(1, 25); ISSUE_FAST(2, 50); }
    else      { ISSUE_SLOW(0);    ISSUE_SLOW(1);     ISSUE_SLOW(2); }

    // ---- Main: 5 groups x 4 chunks (c = 0..19); issue cc = c+3 ----
    // Within group g: cc = 4g+u+3 -> slot (u+3)&3, off25 = 25(u+3) vs rp@100g.
    #pragma unroll 1
    for (int g = 0; g < 5; g++) {
        const int cb = 4 * g;
        #pragma unroll
        for (int u = 0; u < 4; u++) {
            cp_wait2();
            __syncwarp();
            COMPUTE(cb + u, u);
            if (fast) {
                switch (u) {   // compile-time per unrolled slot
                    case 0: ISSUE_FAST(3, 75);  break;
                    case 1: ISSUE_FAST(0, 100); break;
                    case 2: ISSUE_FAST(1, 125); break;
                    case 3: ISSUE_FAST(2, 150); break;
                }
            } else {
                ISSUE_SLOW(cb + u + 3);
            }
        }
        rp0 += 100; rp1 += 100;
    }
    // rp now at group 5 (offset 500 words).

    // ---- Tail: c = 20..24; issues 23 (slot 3, off 575-500=75) and 24
    // (slot 0, off 100); descending waits ----
    cp_wait2(); __syncwarp(); COMPUTE(20, 0);
    if (fast) ISSUE_FAST(3, 75);  else ISSUE_SLOW(23);
    cp_wait2(); __syncwarp(); COMPUTE(21, 1);
    if (fast) ISSUE_FAST(0, 100); else ISSUE_SLOW(24);
    cp_wait2(); __syncwarp(); COMPUTE(22, 2);
    cp_wait1(); __syncwarp(); COMPUTE(23, 3);
    cp_wait0(); __syncwarp(); COMPUTE(24, 0);

    __syncthreads();

    // ---- Coalesced flush ----
    const long long outBase = (long long)blockIdx.x * ROWSPB * S_LEN;
    const long long nBS = (long long)B * S_LEN;
    #pragma unroll
    for (int k = 0; k < 7; k++) {
        int i = t + 256 * k;
        if (i < ROWSPB * S_LEN) {
            long long g2 = outBase + i;
            if (g2 < nBS) {
                out[g2]       = (float)s_act[i];
                out[nBS + g2] = s_val[i];
            }
        }
    }
#undef ISSUE_SLOW
#undef ISSUE_FAST
#undef COMPUTE
}

extern "C" void kernel_launch(void* const* d_in, const int* in_sizes, int n_in,
                              void* d_out, int out_size) {
    const float* in = (const float*)d_in[0];
    float* out = (float*)d_out;
    int B = in_sizes[0] / ROW_ELEMS;
    int blocks = (B + ROWSPB - 1) / ROWSPB;

    static bool attr_done = false;
    if (!attr_done) {
        cudaFuncSetAttribute(greedy_argmax_v11b,
                             cudaFuncAttributePreferredSharedMemoryCarveout,
                             cudaSharedmemCarveoutMaxShared);
        attr_done = true;
    }
    greedy_argmax_v11b<<<blocks, TPB>>>(in, out, B);
}